// round 9
// baseline (speedup 1.0000x reference)
#include <cuda_runtime.h>
#include <cuda_bf16.h>
#include <math.h>

#define B_SZ 256
#define L_SZ 16384
#define NCHUNK 8
#define CS (L_SZ / NCHUNK)          // 2048 positions per chunk, 2 iters/thread
#define NPART 10                    // 6 mat entries + 3 counts + ce

// Fixed-point scales (integer atomics => order-independent, deterministic)
#define MAT_SCALE  1099511627776.0    // 2^40
#define CE_SCALE   33554432.0         // 2^25
#define DMI_SCALE  1125899906842624.0 // 2^50

// Deterministic scratch (all static-zero at first run; finalizer re-zeros
// everything for the next graph replay).
__device__ long long          g_mat[B_SZ][6];   // row-major 3x2 (cols 0,1 of each row)
__device__ unsigned long long g_npack[B_SZ];    // n0 | n1<<21 | n2<<42
__device__ int                g_rowtick[B_SZ];
__device__ unsigned long long g_ce_acc;
__device__ unsigned long long g_cnt_acc;
__device__ unsigned long long g_dmi_acc;
__device__ int                g_done;

__device__ __forceinline__ float frcp(float x) {
    float r;
    asm("rcp.approx.f32 %0, %1;" : "=f"(r) : "f"(x));
    return r;
}

__device__ __forceinline__ void atomic_add_ll(long long* p, long long v) {
    atomicAdd((unsigned long long*)p, (unsigned long long)v);   // exact mod 2^64
}

struct Tok {
    float s3;      // e0+e1+e2
    float s4v;     // valid ? s3+e3 : 1.0f   (for batched log)
    float e0, e1;
    int   lab;
    float xl;      // logit of the label (only meaningful when valid)
    bool  valid;
};

__device__ __forceinline__ Tok prep(float x0, float x1, float x2, float x3, int lab) {
    Tok t;
    float e0 = __expf(x0);
    float e1 = __expf(x1);
    float e2 = __expf(x2);
    float e3 = __expf(x3);
    t.s3 = e0 + e1 + e2;
    t.e0 = e0; t.e1 = e1;
    t.lab = lab;
    t.valid = (lab != 3);
    t.s4v = t.valid ? (t.s3 + e3) : 1.0f;
    t.xl = (lab == 0) ? x0 : (lab == 1) ? x1 : x2;
    return t;
}

__device__ __forceinline__ void accum(const Tok& t, float q,
                                      float acc[6], int n[3]) {
    float p0 = t.e0 * q;
    float p1 = t.e1 * q;
    if (t.lab == 0) { acc[0] += p0; acc[1] += p1; n[0]++; }
    else if (t.lab == 1) { acc[2] += p0; acc[3] += p1; n[1]++; }
    else if (t.lab == 2) { acc[4] += p0; acc[5] += p1; n[2]++; }
}

__device__ __forceinline__ void compute4(
    const float4& a0, const float4& a1, const float4& a2, const float4& a3,
    const int4& lb, float acc[6], int n[3], float& ce)
{
    Tok ta = prep(a0.x, a1.x, a2.x, a3.x, lb.x);
    Tok tb = prep(a0.y, a1.y, a2.y, a3.y, lb.y);
    Tok tc = prep(a0.z, a1.z, a2.z, a3.z, lb.z);
    Tok td = prep(a0.w, a1.w, a2.w, a3.w, lb.w);

    float prod = (ta.s4v * tb.s4v) * (tc.s4v * td.s4v);
    ce += __logf(prod);
    if (ta.valid) ce -= ta.xl;
    if (tb.valid) ce -= tb.xl;
    if (tc.valid) ce -= tc.xl;
    if (td.valid) ce -= td.xl;

    float rab = frcp(ta.s3 * tb.s3);
    float qa = rab * tb.s3;
    float qb = rab * ta.s3;
    float rcd = frcp(tc.s3 * td.s3);
    float qc = rcd * td.s3;
    float qd = rcd * tc.s3;

    accum(ta, qa, acc, n);
    accum(tb, qb, acc, n);
    accum(tc, qc, acc, n);
    accum(td, qd, acc, n);
}

__global__ __launch_bounds__(256, 4) void k2_main(
    const float* __restrict__ pred, const int* __restrict__ labels,
    float* __restrict__ out)
{
    const int tid = threadIdx.x;
    const int ch = blockIdx.x;
    const int b  = blockIdx.y;

    const float* P  = pred + (size_t)b * 4 * L_SZ + ch * CS;
    const int*   Lb = labels + (size_t)b * L_SZ + ch * CS;

    float acc[6];
#pragma unroll
    for (int i = 0; i < 6; ++i) acc[i] = 0.0f;
    int n[3] = {0, 0, 0};
    float ce = 0.0f;

    // Front-batch: both iterations' labels, both ballots, then both groups of
    // pred loads — one exposed DRAM round-trip per block instead of two.
    const int l0 = tid * 4;
    const int l1 = 1024 + tid * 4;
    int4 lb0 = *reinterpret_cast<const int4*>(Lb + l0);
    int4 lb1 = *reinterpret_cast<const int4*>(Lb + l1);
    bool av0 = (lb0.x != 3) | (lb0.y != 3) | (lb0.z != 3) | (lb0.w != 3);
    bool av1 = (lb1.x != 3) | (lb1.y != 3) | (lb1.z != 3) | (lb1.w != 3);
    unsigned bal0 = __ballot_sync(0xFFFFFFFFu, av0);
    unsigned bal1 = __ballot_sync(0xFFFFFFFFu, av1);

    float4 b00, b01, b02, b03, b10, b11, b12, b13;
    if (bal0) {
        b00 = *reinterpret_cast<const float4*>(P + l0);
        b01 = *reinterpret_cast<const float4*>(P + L_SZ + l0);
        b02 = *reinterpret_cast<const float4*>(P + 2 * L_SZ + l0);
        b03 = *reinterpret_cast<const float4*>(P + 3 * L_SZ + l0);
    }
    if (bal1) {
        b10 = *reinterpret_cast<const float4*>(P + l1);
        b11 = *reinterpret_cast<const float4*>(P + L_SZ + l1);
        b12 = *reinterpret_cast<const float4*>(P + 2 * L_SZ + l1);
        b13 = *reinterpret_cast<const float4*>(P + 3 * L_SZ + l1);
    }

    if (bal0) compute4(b00, b01, b02, b03, lb0, acc, n, ce);
    if (bal1) compute4(b10, b11, b12, b13, lb1, acc, n, ce);

    // Block reduction of 10 values: warp shuffle then cross-warp via smem.
    float vals[NPART];
#pragma unroll
    for (int i = 0; i < 6; ++i) vals[i] = acc[i];
    vals[6] = (float)n[0];
    vals[7] = (float)n[1];
    vals[8] = (float)n[2];
    vals[9] = ce;

#pragma unroll
    for (int i = 0; i < NPART; ++i) {
#pragma unroll
        for (int off = 16; off > 0; off >>= 1)
            vals[i] += __shfl_xor_sync(0xFFFFFFFFu, vals[i], off);
    }

    __shared__ float sm[8][NPART];
    __shared__ int   s_last;
    __shared__ float s_loss;
    const int wid = tid >> 5, lane = tid & 31;
    if (lane == 0) {
#pragma unroll
        for (int i = 0; i < NPART; ++i) sm[wid][i] = vals[i];
    }
    if (tid == 0) s_last = 0;
    __syncthreads();

    if (tid == 0) {
        float r[NPART];
#pragma unroll
        for (int i = 0; i < NPART; ++i) {
            float s = 0.0f;
#pragma unroll
            for (int w = 0; w < 8; ++w) s += sm[w][i];
            r[i] = s;
        }

        // Publish this block's partials as exact fixed-point integer adds.
#pragma unroll
        for (int i = 0; i < 6; ++i)
            atomic_add_ll(&g_mat[b][i], (long long)((double)r[i] * MAT_SCALE));
        // counts <= 16384 total per row: pack 3x21 bits, one atomic
        unsigned long long np = (unsigned long long)(int)r[6]
                              | ((unsigned long long)(int)r[7] << 21)
                              | ((unsigned long long)(int)r[8] << 42);
        atomicAdd(&g_npack[b], np);
        atomicAdd(&g_ce_acc, (unsigned long long)(long long)((double)r[9] * CE_SCALE));
        __threadfence();
        int t = atomicAdd(&g_rowtick[b], 1);

        if (t == NCHUNK - 1) {
            // ---- Row finalize: this block completed row b ----
            const double inv_ms = 1.0 / MAT_SCALE;
            double m0 = (double)__ldcg(&g_mat[b][0]) * inv_ms;
            double m1 = (double)__ldcg(&g_mat[b][1]) * inv_ms;
            double m2 = (double)__ldcg(&g_mat[b][2]) * inv_ms;
            double m3 = (double)__ldcg(&g_mat[b][3]) * inv_ms;
            double m4 = (double)__ldcg(&g_mat[b][4]) * inv_ms;
            double m5 = (double)__ldcg(&g_mat[b][5]) * inv_ms;
            unsigned long long npk = __ldcg(&g_npack[b]);
            long long n0 = (long long)(npk & 0x1FFFFFULL);
            long long n1 = (long long)((npk >> 21) & 0x1FFFFFULL);
            long long n2 = (long long)((npk >> 42) & 0x1FFFFFULL);
            long long j  = n0 + n1 + n2;   // == first-pad index (suffix pads)

            double a0 = m0, a1 = m1, a2 = (double)n0 - m0 - m1;
            double b0 = m2, b1 = m3, b2 = (double)n1 - m2 - m3;
            double c0 = m4, c1 = m5, c2 = (double)n2 - m4 - m5;

            double det = a0 * (b1 * c2 - b2 * c1)
                       - a1 * (b0 * c2 - b2 * c0)
                       + a2 * (b0 * c1 - b1 * c0);
            double jf = (double)j;
            double dets = det / (jf * jf * jf);

            float arg = (float)fabs(dets) + 1e-3f;
            float lg = __logf(arg);
            float dmi = (dets < 0.0) ? lg : -lg;

            atomicAdd(&g_dmi_acc, (unsigned long long)(long long)((double)dmi * DMI_SCALE));
            atomicAdd(&g_cnt_acc, (unsigned long long)j);
            __threadfence();
            int d = atomicAdd(&g_done, 1);

            if (d == B_SZ - 1) {
                // ---- Global finalize ----
                long long dmi_s = (long long)__ldcg(&g_dmi_acc);
                long long ce_s  = (long long)__ldcg(&g_ce_acc);
                long long cnt_s = (long long)__ldcg(&g_cnt_acc);
                double loss = 0.1 * ((double)dmi_s / DMI_SCALE / (double)B_SZ)
                            + ((double)ce_s / CE_SCALE) / (double)cnt_s;
                s_loss = (float)loss;
                s_last = 1;
            }
        }
    }
    __syncthreads();

    if (s_last) {
        // Cooperative reset of all scratch for the next graph replay.
        const int r = tid;   // 256 threads, one row each
#pragma unroll
        for (int i = 0; i < 6; ++i) g_mat[r][i] = 0;
        g_npack[r] = 0ULL;
        g_rowtick[r] = 0;
        if (tid == 0) {
            g_ce_acc = 0ULL;
            g_cnt_acc = 0ULL;
            g_dmi_acc = 0ULL;
            g_done = 0;
            out[0] = s_loss;
        }
    }
}

extern "C" void kernel_launch(void* const* d_in, const int* in_sizes, int n_in,
                              void* d_out, int out_size) {
    const float* pred;
    const int*   labels;
    if (in_sizes[0] == B_SZ * 4 * L_SZ) {
        pred   = (const float*)d_in[0];
        labels = (const int*)d_in[1];
    } else {
        pred   = (const float*)d_in[1];
        labels = (const int*)d_in[0];
    }
    float* out = (float*)d_out;

    dim3 g2(NCHUNK, B_SZ);
    k2_main<<<g2, 256>>>(pred, labels, out);
}

// round 10
// speedup vs baseline: 1.1780x; 1.1780x over previous
#include <cuda_runtime.h>
#include <cuda_bf16.h>
#include <math.h>

#define B_SZ 256
#define L_SZ 16384
#define NCHUNK 8
#define CS (L_SZ / NCHUNK)          // 2048 positions per chunk, 2 iters/thread
#define NPART 10                    // 6 mat entries + 3 counts + ce

// Scratch: g_part[(c*NPART + i) * B_SZ + b]  (lane-coalesced over b)
__device__ float g_part[NCHUNK * NPART * B_SZ];

__device__ __forceinline__ float frcp(float x) {
    float r;
    asm("rcp.approx.f32 %0, %1;" : "=f"(r) : "f"(x));
    return r;
}

// Process a PAIR of tokens: shared rcp (Montgomery), returns product of the
// two tokens' s4v terms (for the per-iteration batched log). Counts go into
// npack as 10-bit fields (per-thread max 8/class, warp sum max 256: fits).
__device__ __forceinline__ float compute2(
    float ax0, float ax1, float ax2, float ax3, int laba,
    float bx0, float bx1, float bx2, float bx3, int labb,
    float acc[6], unsigned& npack, float& ce)
{
    float ea0 = __expf(ax0), ea1 = __expf(ax1), ea2 = __expf(ax2), ea3 = __expf(ax3);
    float eb0 = __expf(bx0), eb1 = __expf(bx1), eb2 = __expf(bx2), eb3 = __expf(bx3);
    float sa3 = ea0 + ea1 + ea2;
    float sb3 = eb0 + eb1 + eb2;
    bool va = (laba != 3), vb = (labb != 3);
    float sa4 = va ? (sa3 + ea3) : 1.0f;
    float sb4 = vb ? (sb3 + eb3) : 1.0f;
    float xla = (laba == 0) ? ax0 : (laba == 1) ? ax1 : ax2;
    float xlb = (labb == 0) ? bx0 : (labb == 1) ? bx1 : bx2;
    if (va) ce -= xla;
    if (vb) ce -= xlb;

    float r  = frcp(sa3 * sb3);
    float qa = r * sb3;
    float qb = r * sa3;
    float pa0 = ea0 * qa, pa1 = ea1 * qa;
    float pb0 = eb0 * qb, pb1 = eb1 * qb;

    if (laba == 0)      { acc[0] += pa0; acc[1] += pa1; npack += 1u; }
    else if (laba == 1) { acc[2] += pa0; acc[3] += pa1; npack += (1u << 10); }
    else if (laba == 2) { acc[4] += pa0; acc[5] += pa1; npack += (1u << 20); }
    if (labb == 0)      { acc[0] += pb0; acc[1] += pb1; npack += 1u; }
    else if (labb == 1) { acc[2] += pb0; acc[3] += pb1; npack += (1u << 10); }
    else if (labb == 2) { acc[4] += pb0; acc[5] += pb1; npack += (1u << 20); }

    return sa4 * sb4;
}

__global__ __launch_bounds__(256, 5) void k2_main(
    const float* __restrict__ pred, const int* __restrict__ labels)
{
    const int tid = threadIdx.x;
    const int ch = blockIdx.x;
    const int b  = blockIdx.y;

    const float* P  = pred + (size_t)b * 4 * L_SZ + ch * CS;
    const int*   Lb = labels + (size_t)b * L_SZ + ch * CS;

    float acc[6];
#pragma unroll
    for (int i = 0; i < 6; ++i) acc[i] = 0.0f;
    unsigned npack = 0u;
    float ce = 0.0f;

    // Front-batch both iterations' labels + ballots (cheap, coalesced).
    const int l0 = tid * 4;
    const int l1 = 1024 + tid * 4;
    int4 lb0 = *reinterpret_cast<const int4*>(Lb + l0);
    int4 lb1 = *reinterpret_cast<const int4*>(Lb + l1);
    bool av0 = (lb0.x != 3) | (lb0.y != 3) | (lb0.z != 3) | (lb0.w != 3);
    bool av1 = (lb1.x != 3) | (lb1.y != 3) | (lb1.z != 3) | (lb1.w != 3);
    unsigned bal0 = __ballot_sync(0xFFFFFFFFu, av0);
    unsigned bal1 = __ballot_sync(0xFFFFFFFFu, av1);

    if (bal0) {
        float4 a0 = *reinterpret_cast<const float4*>(P + l0);
        float4 a1 = *reinterpret_cast<const float4*>(P + L_SZ + l0);
        float4 a2 = *reinterpret_cast<const float4*>(P + 2 * L_SZ + l0);
        float4 a3 = *reinterpret_cast<const float4*>(P + 3 * L_SZ + l0);
        float p01 = compute2(a0.x, a1.x, a2.x, a3.x, lb0.x,
                             a0.y, a1.y, a2.y, a3.y, lb0.y, acc, npack, ce);
        float p23 = compute2(a0.z, a1.z, a2.z, a3.z, lb0.z,
                             a0.w, a1.w, a2.w, a3.w, lb0.w, acc, npack, ce);
        ce += __logf(p01 * p23);
    }
    if (bal1) {
        float4 a0 = *reinterpret_cast<const float4*>(P + l1);
        float4 a1 = *reinterpret_cast<const float4*>(P + L_SZ + l1);
        float4 a2 = *reinterpret_cast<const float4*>(P + 2 * L_SZ + l1);
        float4 a3 = *reinterpret_cast<const float4*>(P + 3 * L_SZ + l1);
        float p01 = compute2(a0.x, a1.x, a2.x, a3.x, lb1.x,
                             a0.y, a1.y, a2.y, a3.y, lb1.y, acc, npack, ce);
        float p23 = compute2(a0.z, a1.z, a2.z, a3.z, lb1.z,
                             a0.w, a1.w, a2.w, a3.w, lb1.w, acc, npack, ce);
        ce += __logf(p01 * p23);
    }

    // Warp reduction: 7 floats + 1 packed int (vs 10 floats before).
#pragma unroll
    for (int off = 16; off > 0; off >>= 1) {
#pragma unroll
        for (int i = 0; i < 6; ++i)
            acc[i] += __shfl_xor_sync(0xFFFFFFFFu, acc[i], off);
        ce    += __shfl_xor_sync(0xFFFFFFFFu, ce, off);
        npack += __shfl_xor_sync(0xFFFFFFFFu, npack, off);
    }

    __shared__ float sm[8][NPART];
    const int wid = tid >> 5, lane = tid & 31;
    if (lane == 0) {
#pragma unroll
        for (int i = 0; i < 6; ++i) sm[wid][i] = acc[i];
        sm[wid][6] = (float)(npack & 1023u);
        sm[wid][7] = (float)((npack >> 10) & 1023u);
        sm[wid][8] = (float)((npack >> 20) & 1023u);
        sm[wid][9] = ce;
    }
    __syncthreads();
    if (tid == 0) {
#pragma unroll
        for (int i = 0; i < NPART; ++i) {
            float s = 0.0f;
#pragma unroll
            for (int w = 0; w < 8; ++w) s += sm[w][i];
            g_part[(ch * NPART + i) * B_SZ + b] = s;
        }
    }
}

// ---------------- K3: finalize (cheap in wall time; ncu inflates it) -------
__global__ __launch_bounds__(1024) void k3_final(float* __restrict__ out) {
    if (blockIdx.x != 0) return;

    const int tid = threadIdx.x;
    const int g   = tid >> 8;       // 0..3
    const int b   = tid & 255;      // row

    // Batched prefetch: 20 independent loads, no consumer in between.
    float v[20];
#pragma unroll
    for (int cc = 0; cc < 2; ++cc) {
        const int c = g * 2 + cc;
#pragma unroll
        for (int i = 0; i < NPART; ++i)
            v[cc * NPART + i] = g_part[(c * NPART + i) * B_SZ + b];
    }

    __shared__ float smg[4][NPART][B_SZ];    // 40KB, b lane-major: conflict-free
#pragma unroll
    for (int i = 0; i < NPART; ++i)
        smg[g][i][b] = v[i] + v[NPART + i];
    __syncthreads();

    __shared__ double s_dmi[B_SZ];
    __shared__ double s_ce[B_SZ];
    __shared__ double s_cnt[B_SZ];

    if (g == 0) {
        float m[NPART];
#pragma unroll
        for (int i = 0; i < NPART; ++i)
            m[i] = (smg[0][i][b] + smg[1][i][b]) + (smg[2][i][b] + smg[3][i][b]);

        float n0 = m[6], n1 = m[7], n2 = m[8], ce = m[9];
        float cnt = n0 + n1 + n2;   // == j (pads are a suffix, always present)

        // 3x3 rows (raw sums); col2 from row counts; det(M/j)=det(M)/j^3
        double a0 = m[0], a1 = m[1], a2 = (double)n0 - m[0] - m[1];
        double b0 = m[2], b1 = m[3], b2 = (double)n1 - m[2] - m[3];
        double c0 = m[4], c1 = m[5], c2 = (double)n2 - m[4] - m[5];

        double det = a0 * (b1 * c2 - b2 * c1)
                   - a1 * (b0 * c2 - b2 * c0)
                   + a2 * (b0 * c1 - b1 * c0);
        double jf = (double)cnt;
        double dets = det / (jf * jf * jf);

        float arg = (float)fabs(dets) + 1e-3f;
        float lg = __logf(arg);
        float dmi = (dets < 0.0) ? lg : -lg;

        s_dmi[b] = (double)dmi;
        s_ce[b]  = (double)ce;
        s_cnt[b] = (double)cnt;
    }
    __syncthreads();

    for (int s = 128; s > 0; s >>= 1) {
        if (tid < s) {
            s_dmi[tid] += s_dmi[tid + s];
            s_ce[tid]  += s_ce[tid + s];
            s_cnt[tid] += s_cnt[tid + s];
        }
        __syncthreads();
    }
    if (tid == 0) {
        double loss = 0.1 * (s_dmi[0] / (double)B_SZ) + s_ce[0] / s_cnt[0];
        out[0] = (float)loss;
    }
}

extern "C" void kernel_launch(void* const* d_in, const int* in_sizes, int n_in,
                              void* d_out, int out_size) {
    const float* pred;
    const int*   labels;
    if (in_sizes[0] == B_SZ * 4 * L_SZ) {
        pred   = (const float*)d_in[0];
        labels = (const int*)d_in[1];
    } else {
        pred   = (const float*)d_in[1];
        labels = (const int*)d_in[0];
    }
    float* out = (float*)d_out;

    dim3 g2(NCHUNK, B_SZ);
    k2_main<<<g2, 256>>>(pred, labels);
    k3_final<<<160, 1024>>>(out);
}